// round 11
// baseline (speedup 1.0000x reference)
#include <cuda_runtime.h>
#include <cuda_fp16.h>
#include <math.h>
#include <stdint.h>

// ---------------------------------------------------------------------------
// QBNN attention, all-fp16 tensor-core pipeline. B=2, S=2048, E=1024, H=16, hd=64.
//  0) convert: x -> fp16 ; W* -> transposed fp16 (fused 4-way)
//  1) gemm_fp16 fused: QKV = x@[Wq|Wk|Wv] + b  (one launch, N=3072)
//  2) prep: Qcat(log2e)/Kcat fp16, Vt fp16   (transposed-J float4 matmul)
//  3) flash16: 256-row q-tiles, 16 warps, fp16 mma, log2-domain softmax
//  4) gemm_fp16: out = O@Wo + bo (fp32 out)
// ---------------------------------------------------------------------------

#define N_TOK   4096
#define EMB     1024
#define HEADS   16
#define HD      64
#define SEQ     2048
#define BH      32
#define LOG2E   1.4426950408889634f

// fp16 scratch arena
#define HX     0
#define HW     (HX    + N_TOK*EMB)           // 4 transposed weights
#define HQKV   (HW    + 4*EMB*EMB)           // [4096][3072]
#define HQC    (HQKV  + N_TOK*3*EMB)
#define HKC    (HQC   + BH*SEQ*128)
#define HVT    (HKC   + BH*SEQ*128)
#define HO     (HVT   + BH*64*SEQ)
#define HTOTAL (HO    + N_TOK*EMB)
__device__ __half g_hscratch[HTOTAL];

// ---------------------------------------------------------------------------
// convert: fp32 -> fp16 elementwise
// ---------------------------------------------------------------------------
__global__ __launch_bounds__(256)
void convert_kernel(const float* __restrict__ src, __half* __restrict__ dst, int n4)
{
    int i = blockIdx.x * blockDim.x + threadIdx.x;
    if (i >= n4) return;
    float4 v = ((const float4*)src)[i];
    __half2 h0 = __floats2half2_rn(v.x, v.y);
    __half2 h1 = __floats2half2_rn(v.z, v.w);
    uint2 w;
    w.x = *(uint32_t*)&h0;
    w.y = *(uint32_t*)&h1;
    ((uint2*)dst)[i] = w;
}

// ---------------------------------------------------------------------------
// fused transpose+convert of all 4 weights: W[k][n] fp32 -> Wt[n][k] fp16
// ---------------------------------------------------------------------------
__global__ __launch_bounds__(256)
void transpose4_kernel(const float* __restrict__ W0, const float* __restrict__ W1,
                       const float* __restrict__ W2, const float* __restrict__ W3,
                       __half* __restrict__ Tbase)
{
    __shared__ float tile[32][33];
    int z  = blockIdx.z;
    const float* W = (z == 0) ? W0 : (z == 1) ? W1 : (z == 2) ? W2 : W3;
    __half* T = Tbase + (size_t)z * EMB * EMB;

    int k0 = blockIdx.y * 32;
    int n0 = blockIdx.x * 32;
    int tx = threadIdx.x & 31;
    int ty = threadIdx.x >> 5;
#pragma unroll
    for (int j = 0; j < 4; j++)
        tile[ty + j * 8][tx] = W[(size_t)(k0 + ty + j * 8) * EMB + n0 + tx];
    __syncthreads();
#pragma unroll
    for (int j = 0; j < 4; j++) {
        int n = ty + j * 8;
        T[(size_t)(n0 + n) * EMB + k0 + tx] = __float2half(tile[tx][n]);
    }
}

// ---------------------------------------------------------------------------
// helpers
// ---------------------------------------------------------------------------
#define MMA16816H(d, a0, a1, a2, a3, b0, b1)                                 \
    asm volatile(                                                            \
        "mma.sync.aligned.m16n8k16.row.col.f32.f16.f16.f32 "                 \
        "{%0,%1,%2,%3}, {%4,%5,%6,%7}, {%8,%9}, {%0,%1,%2,%3};"              \
        : "+f"(d[0]), "+f"(d[1]), "+f"(d[2]), "+f"(d[3])                     \
        : "r"(a0), "r"(a1), "r"(a2), "r"(a3), "r"(b0), "r"(b1))

#define LDSM_X4(r0, r1, r2, r3, addr)                                        \
    asm volatile("ldmatrix.sync.aligned.m8n8.x4.shared.b16 {%0,%1,%2,%3}, [%4];" \
        : "=r"(r0), "=r"(r1), "=r"(r2), "=r"(r3) : "r"(addr))

__device__ __forceinline__ void cp16s(uint32_t smem_dst, const void* gmem_src)
{
    asm volatile("cp.async.cg.shared.global [%0], [%1], 16;"
                 :: "r"(smem_dst), "l"(gmem_src));
}

__device__ __forceinline__ uint32_t h2exp2(uint32_t x)
{
    uint32_t r;
    asm("ex2.approx.f16x2 %0, %1;" : "=r"(r) : "r"(x));
    return r;
}

__device__ __forceinline__ float tanh_fast(float x)
{
    float r;
    asm("tanh.approx.f32 %0, %1;" : "=f"(r) : "f"(x));
    return r;
}

// ---------------------------------------------------------------------------
// Single-pass fp16 tensor-core GEMM, fused-N capable.
// C[4096 x outN slice] = A@Bt + bias. Section (n0>>10) selects bias pointer.
// ---------------------------------------------------------------------------
#define GSTAGE  32768
#define GSMEM   (3 * GSTAGE)

__global__ __launch_bounds__(256, 2)
void gemm_fp16(const __half* __restrict__ A, const __half* __restrict__ Bt,
               const float* __restrict__ b0p, const float* __restrict__ b1p,
               const float* __restrict__ b2p,
               void* __restrict__ Cout, int outN, int half_out)
{
    extern __shared__ __align__(1024) char smem[];
    const int K = 1024;
    uint32_t sbase;
    asm("{ .reg .u64 t; cvta.to.shared.u64 t, %1; cvt.u32.u64 %0, t; }"
        : "=r"(sbase) : "l"(smem));

    int tid  = threadIdx.x;
    int warp = tid >> 5;
    int lane = tid & 31;
    int wm   = warp & 1;
    int wn   = warp >> 1;
    int m0   = blockIdx.y * 128;
    int n0   = blockIdx.x * 128;

    int sec = n0 >> 10;
    const float* bias = (sec == 0) ? b0p : (sec == 1) ? b1p : b2p;
    int nloc = n0 & 1023;

    float acc[4][4][4];
#pragma unroll
    for (int mi = 0; mi < 4; mi++)
#pragma unroll
        for (int nj = 0; nj < 4; nj++)
#pragma unroll
            for (int t = 0; t < 4; t++) acc[mi][nj][t] = 0.f;

    auto issue = [&](int chunk, int stg) {
        int k0 = chunk << 6;
        const __half* Ap = A  + (size_t)m0 * K + k0;
        const __half* Bp = Bt + (size_t)n0 * K + k0;
        uint32_t aBuf = sbase + stg * GSTAGE;
        uint32_t bBuf = aBuf + 16384;
#pragma unroll
        for (int i = 0; i < 4; i++) {
            int idx = tid + i * 256;
            int r   = idx >> 3;
            int c   = idx & 7;
            uint32_t sw = (uint32_t)(r << 7) | ((uint32_t)(c ^ (r & 7)) << 4);
            cp16s(aBuf + sw, Ap + (size_t)r * K + c * 8);
            cp16s(bBuf + sw, Bp + (size_t)r * K + c * 8);
        }
        asm volatile("cp.async.commit_group;");
    };

    issue(0, 0);
    issue(1, 1);

    int lm  = lane >> 3;
    int lr  = lane & 7;

    for (int t = 0; t < 16; t++) {
        int stg = t % 3;
        if (t < 15) asm volatile("cp.async.wait_group 1;");
        else        asm volatile("cp.async.wait_group 0;");
        __syncthreads();

        uint32_t aBuf = sbase + stg * GSTAGE;
        uint32_t bBuf = aBuf + 16384;

#pragma unroll
        for (int kk = 0; kk < 64; kk += 16) {
            int kc = kk >> 3;
            uint32_t af[4][4];
#pragma unroll
            for (int mi = 0; mi < 4; mi++) {
                int row = wm * 64 + mi * 16 + (lm & 1) * 8 + lr;
                int ch  = kc + (lm >> 1);
                uint32_t ad = aBuf + (uint32_t)(row << 7) + ((uint32_t)(ch ^ (row & 7)) << 4);
                LDSM_X4(af[mi][0], af[mi][1], af[mi][2], af[mi][3], ad);
            }
            uint32_t bf_[4][2];
#pragma unroll
            for (int njp = 0; njp < 2; njp++) {
                int row = wn * 32 + njp * 16 + (lm >> 1) * 8 + lr;
                int ch  = kc + (lm & 1);
                uint32_t bd = bBuf + (uint32_t)(row << 7) + ((uint32_t)(ch ^ (row & 7)) << 4);
                LDSM_X4(bf_[njp * 2][0], bf_[njp * 2][1],
                        bf_[njp * 2 + 1][0], bf_[njp * 2 + 1][1], bd);
            }
#pragma unroll
            for (int mi = 0; mi < 4; mi++)
#pragma unroll
                for (int nj = 0; nj < 4; nj++)
                    MMA16816H(acc[mi][nj], af[mi][0], af[mi][1], af[mi][2], af[mi][3],
                              bf_[nj][0], bf_[nj][1]);
        }

        if (t + 2 < 16) issue(t + 2, (t + 2) % 3);
    }

    int g  = lane >> 2;
    int tq = lane & 3;
#pragma unroll
    for (int mi = 0; mi < 4; mi++) {
        size_t r0 = (size_t)(m0 + wm * 64 + mi * 16 + g);
        size_t r1 = r0 + 8;
#pragma unroll
        for (int nj = 0; nj < 4; nj++) {
            int cl = wn * 32 + nj * 8 + tq * 2;
            float b0 = bias[nloc + cl], b1 = bias[nloc + cl + 1];
            int c  = n0 + cl;
            float v00 = acc[mi][nj][0] + b0, v01 = acc[mi][nj][1] + b1;
            float v10 = acc[mi][nj][2] + b0, v11 = acc[mi][nj][3] + b1;
            if (half_out) {
                __half* C = (__half*)Cout;
                *(__half2*)&C[r0 * outN + c] = __floats2half2_rn(v00, v01);
                *(__half2*)&C[r1 * outN + c] = __floats2half2_rn(v10, v11);
            } else {
                float* C = (float*)Cout;
                *(float2*)&C[r0 * outN + c] = make_float2(v00, v01);
                *(float2*)&C[r1 * outN + c] = make_float2(v10, v11);
            }
        }
    }
}

// ---------------------------------------------------------------------------
// prep: reads fused QKV [tok][3072]. Transposed-J (stride 68) float4 matmul.
// ---------------------------------------------------------------------------
__global__ __launch_bounds__(512)
void prep_kernel(const __half* __restrict__ QKV, const float* __restrict__ J,
                 const float* __restrict__ lamp,
                 __half* __restrict__ Qc, __half* __restrict__ Kc,
                 __half* __restrict__ Vt)
{
    __shared__ float Jst[64 * 68];   // J transposed: Jst[e][dd], stride 68
    __shared__ float qn[8][64];

    int h   = blockIdx.y;
    int d   = threadIdx.x;
    int ty  = threadIdx.y;
    int tid = ty * 64 + d;

    // J[h] row-major [dd][e] -> Jst[e*68+dd] (coalesced read)
    for (int i = tid; i < 4096; i += 512)
        Jst[(i & 63) * 68 + (i >> 6)] = J[h * 4096 + i];

    int tok = blockIdx.x * 8 + ty;
    int b   = tok >> 11;
    int s   = tok & 2047;
    int bh  = (b << 4) + h;

    const __half* row = QKV + (size_t)tok * 3072 + h * HD + d;
    float q = __half2float(row[0]);
    float k = __half2float(row[1024]);
    __half v = row[2048];
    qn[ty][d] = tanh_fast(q);
    __syncthreads();

    float accv = 0.f;
#pragma unroll
    for (int dd = 0; dd < 64; dd += 4) {
        float4 jv = *(const float4*)&Jst[d * 68 + dd];
        float4 qv = *(const float4*)&qn[ty][dd];
        accv += qv.x * jv.x + qv.y * jv.y + qv.z * jv.z + qv.w * jv.w;
    }

    float lam = lamp[0];
    size_t base = (size_t)bh * SEQ + s;
    Qc[base * 128 + d]      = __float2half(q * 0.125f * LOG2E);
    Qc[base * 128 + 64 + d] = __float2half(lam * accv * LOG2E);
    Kc[base * 128 + d]      = __float2half(k);
    Kc[base * 128 + 64 + d] = __float2half(tanh_fast(k));
    Vt[((size_t)bh * 64 + d) * SEQ + s] = v;
}

// ---------------------------------------------------------------------------
// flash16: 256-row q-tiles, 16 warps (512 thr), fp16 mma, log2 softmax.
// smem: Q 64KB (two 256x64 halves) + 3 stages x (K 16KB + V 8KB) = 136KB.
// ---------------------------------------------------------------------------
#define FLQ_BYTES  65536
#define FLSTAGE    24576
#define FL16_SMEM  (FLQ_BYTES + 3 * FLSTAGE)

__global__ __launch_bounds__(512, 1)
void flash16_kernel(const __half* __restrict__ Qc, const __half* __restrict__ Kc,
                    const __half* __restrict__ Vt, __half* __restrict__ O)
{
    extern __shared__ __align__(1024) char smem[];
    uint32_t sbase;
    asm("{ .reg .u64 t; cvta.to.shared.u64 t, %1; cvt.u32.u64 %0, t; }"
        : "=r"(sbase) : "l"(smem));

    int tid  = threadIdx.x;
    int w    = tid >> 5;              // 0..15
    int lane = tid & 31;
    int lm   = lane >> 3;
    int lr   = lane & 7;
    int g    = lane >> 2;
    int tq   = lane & 3;

    int bh    = blockIdx.y;
    int b     = bh >> 4;
    int h     = bh & 15;
    int qtile = (int)gridDim.x - 1 - (int)blockIdx.x;   // heavy first
    int qt0   = qtile * 256;
    int nkt   = 4 * qtile + 4;

    // Q load: 256 rows x 16 chunks = 4096, 8 iters of 512
    const __half* Qg = Qc + ((size_t)bh * SEQ + qt0) * 128;
#pragma unroll
    for (int i = 0; i < 8; i++) {
        int idx = tid + i * 512;
        int r   = idx >> 4;
        int ch  = idx & 15;
        uint32_t dst = sbase + (uint32_t)(ch >> 3) * 32768
                     + (uint32_t)(r << 7) + ((uint32_t)((ch & 7) ^ (r & 7)) << 4);
        cp16s(dst, Qg + (size_t)r * 128 + ch * 8);
    }
    asm volatile("cp.async.commit_group;");

    auto issueKV = [&](int kt, int s) {
        uint32_t kb = sbase + FLQ_BYTES + (uint32_t)s * FLSTAGE;
        uint32_t vb = kb + 16384;
        const __half* Kg = Kc + ((size_t)bh * SEQ + kt * 64) * 128;
        const __half* Vg = Vt + (size_t)bh * 64 * SEQ + kt * 64;
#pragma unroll
        for (int i = 0; i < 2; i++) {
            int idx = tid + i * 512;
            int r   = idx >> 4;
            int ch  = idx & 15;
            uint32_t dst = kb + (uint32_t)(ch >> 3) * 8192
                         + (uint32_t)(r << 7) + ((uint32_t)((ch & 7) ^ (r & 7)) << 4);
            cp16s(dst, Kg + (size_t)r * 128 + ch * 8);
        }
        {
            int r = tid >> 3;
            int c = tid & 7;
            uint32_t dst = vb + (uint32_t)(r << 7) + ((uint32_t)(c ^ (r & 7)) << 4);
            cp16s(dst, Vg + (size_t)r * SEQ + c * 8);
        }
        asm volatile("cp.async.commit_group;");
    };

    issueKV(0, 0);
    issueKV(1, 1);

    asm volatile("cp.async.wait_group 2;");
    __syncthreads();

    uint32_t qf[8][4];
#pragma unroll
    for (int ks = 0; ks < 8; ks++) {
        int half = ks >> 2;
        int kc   = (ks & 3) * 2 + (lm >> 1);
        int row  = w * 16 + (lm & 1) * 8 + lr;
        uint32_t ad = sbase + (uint32_t)half * 32768
                    + (uint32_t)(row << 7) + ((uint32_t)(kc ^ (row & 7)) << 4);
        LDSM_X4(qf[ks][0], qf[ks][1], qf[ks][2], qf[ks][3], ad);
    }

    float oacc[8][4];
#pragma unroll
    for (int nt = 0; nt < 8; nt++)
#pragma unroll
        for (int t = 0; t < 4; t++) oacc[nt][t] = 0.f;
    float mrow[2] = {-1e30f, -1e30f};
    float lrow[2] = {0.f, 0.f};

    int qrow0 = qt0 + w * 16;
    int r0g   = qrow0 + g;

    for (int kt = 0; kt < nkt; kt++) {
        int s_ = kt % 3;
        if (kt + 1 < nkt) asm volatile("cp.async.wait_group 1;");
        else              asm volatile("cp.async.wait_group 0;");
        __syncthreads();

        if (kt + 2 < nkt) issueKV(kt + 2, (kt + 2) % 3);

        uint32_t kb = sbase + FLQ_BYTES + (uint32_t)s_ * FLSTAGE;
        uint32_t vb = kb + 16384;

        float sacc[8][4];
#pragma unroll
        for (int nt = 0; nt < 8; nt++)
#pragma unroll
            for (int t = 0; t < 4; t++) sacc[nt][t] = 0.f;

#pragma unroll
        for (int ks = 0; ks < 8; ks++) {
            int half = ks >> 2;
            int kc   = (ks & 3) * 2 + (lm & 1);
            uint32_t kf[8][2];
#pragma unroll
            for (int nb = 0; nb < 4; nb++) {
                int row = nb * 16 + (lm >> 1) * 8 + lr;
                uint32_t ad = kb + (uint32_t)half * 8192
                            + (uint32_t)(row << 7) + ((uint32_t)(kc ^ (row & 7)) << 4);
                LDSM_X4(kf[nb * 2][0], kf[nb * 2][1],
                        kf[nb * 2 + 1][0], kf[nb * 2 + 1][1], ad);
            }
#pragma unroll
            for (int nt = 0; nt < 8; nt++)
                MMA16816H(sacc[nt], qf[ks][0], qf[ks][1], qf[ks][2], qf[ks][3],
                          kf[nt][0], kf[nt][1]);
        }

        if (kt * 64 + 63 > qrow0) {
#pragma unroll
            for (int nt = 0; nt < 8; nt++) {
                int c0 = kt * 64 + nt * 8 + 2 * tq;
                if (c0     > r0g)     sacc[nt][0] = -1e30f;
                if (c0 + 1 > r0g)     sacc[nt][1] = -1e30f;
                if (c0     > r0g + 8) sacc[nt][2] = -1e30f;
                if (c0 + 1 > r0g + 8) sacc[nt][3] = -1e30f;
            }
        }

        float tm0 = -1e30f, tm1 = -1e30f;
#pragma unroll
        for (int nt = 0; nt < 8; nt++) {
            tm0 = fmaxf(tm0, fmaxf(sacc[nt][0], sacc[nt][1]));
            tm1 = fmaxf(tm1, fmaxf(sacc[nt][2], sacc[nt][3]));
        }
        tm0 = fmaxf(tm0, __shfl_xor_sync(0xffffffffu, tm0, 1));
        tm0 = fmaxf(tm0, __shfl_xor_sync(0xffffffffu, tm0, 2));
        tm1 = fmaxf(tm1, __shfl_xor_sync(0xffffffffu, tm1, 1));
        tm1 = fmaxf(tm1, __shfl_xor_sync(0xffffffffu, tm1, 2));

        float mnew0 = fmaxf(mrow[0], tm0);
        float mnew1 = fmaxf(mrow[1], tm1);
        float corr0 = exp2f(mrow[0] - mnew0);
        float corr1 = exp2f(mrow[1] - mnew1);
        mrow[0] = mnew0;
        mrow[1] = mnew1;
#pragma unroll
        for (int nt = 0; nt < 8; nt++) {
            oacc[nt][0] *= corr0; oacc[nt][1] *= corr0;
            oacc[nt][2] *= corr1; oacc[nt][3] *= corr1;
        }

        uint32_t pf[4][4];
        float ps0 = 0.f, ps1 = 0.f;
#pragma unroll
        for (int nt = 0; nt < 8; nt++) {
            __half2 d0 = __floats2half2_rn(sacc[nt][0] - mnew0, sacc[nt][1] - mnew0);
            __half2 d1 = __floats2half2_rn(sacc[nt][2] - mnew1, sacc[nt][3] - mnew1);
            uint32_t p0 = h2exp2(*(uint32_t*)&d0);
            uint32_t p1 = h2exp2(*(uint32_t*)&d1);
            float2 f0 = __half22float2(*(__half2*)&p0);
            float2 f1 = __half22float2(*(__half2*)&p1);
            ps0 += f0.x + f0.y;
            ps1 += f1.x + f1.y;
            pf[nt >> 1][(nt & 1) * 2]     = p0;
            pf[nt >> 1][(nt & 1) * 2 + 1] = p1;
        }
        ps0 += __shfl_xor_sync(0xffffffffu, ps0, 1);
        ps0 += __shfl_xor_sync(0xffffffffu, ps0, 2);
        ps1 += __shfl_xor_sync(0xffffffffu, ps1, 1);
        ps1 += __shfl_xor_sync(0xffffffffu, ps1, 2);
        lrow[0] = lrow[0] * corr0 + ps0;
        lrow[1] = lrow[1] * corr1 + ps1;

#pragma unroll
        for (int kc16 = 0; kc16 < 4; kc16++) {
            int kc = kc16 * 2 + (lm & 1);
            uint32_t vf[8][2];
#pragma unroll
            for (int nb = 0; nb < 4; nb++) {
                int row = nb * 16 + (lm >> 1) * 8 + lr;
                uint32_t ad = vb + (uint32_t)(row << 7)
                            + ((uint32_t)(kc ^ (row & 7)) << 4);
                LDSM_X4(vf[nb * 2][0], vf[nb * 2][1],
                        vf[nb * 2 + 1][0], vf[nb * 2 + 1][1], ad);
            }
#pragma unroll
            for (int nt = 0; nt < 8; nt++)
                MMA16816H(oacc[nt], pf[kc16][0], pf[kc16][1], pf[kc16][2], pf[kc16][3],
                          vf[nt][0], vf[nt][1]);
        }
    }

    // epilogue: fp16 O token-major
    float inv0 = 1.0f / lrow[0];
    float inv1 = 1.0f / lrow[1];
    size_t rt0 = (size_t)(b * SEQ + qt0 + w * 16 + g);
    __half* O0 = O + rt0 * EMB + h * 64;
    __half* O1 = O0 + (size_t)8 * EMB;
#pragma unroll
    for (int nt = 0; nt < 8; nt++) {
        int c = nt * 8 + 2 * tq;
        *(__half2*)&O0[c] = __floats2half2_rn(oacc[nt][0] * inv0, oacc[nt][1] * inv0);
        *(__half2*)&O1[c] = __floats2half2_rn(oacc[nt][2] * inv1, oacc[nt][3] * inv1);
    }
}

// ---------------------------------------------------------------------------
// launch
// ---------------------------------------------------------------------------
extern "C" void kernel_launch(void* const* d_in, const int* in_sizes, int n_in,
                              void* d_out, int out_size)
{
    const float* x   = (const float*)d_in[0];
    const float* Wq  = (const float*)d_in[1];
    const float* bq  = (const float*)d_in[2];
    const float* Wk  = (const float*)d_in[3];
    const float* bk  = (const float*)d_in[4];
    const float* Wv  = (const float*)d_in[5];
    const float* bv  = (const float*)d_in[6];
    const float* Wo  = (const float*)d_in[7];
    const float* bo  = (const float*)d_in[8];
    const float* J   = (const float*)d_in[9];
    const float* lam = (const float*)d_in[10];
    float* out = (float*)d_out;

    void* p = nullptr;
    cudaGetSymbolAddress(&p, g_hscratch);
    __half* hs    = (__half*)p;
    __half* x16   = hs + HX;
    __half* w16   = hs + HW;
    __half* qkv16 = hs + HQKV;
    __half* qc    = hs + HQC;
    __half* kc    = hs + HKC;
    __half* vt    = hs + HVT;
    __half* o16   = hs + HO;

    const int WSZ = EMB * EMB;
    __half* wo16 = w16 + 3 * WSZ;

    convert_kernel<<<(N_TOK * EMB / 4 + 255) / 256, 256>>>(x, x16, N_TOK * EMB / 4);
    dim3 tg(32, 32, 4), tb(256);
    transpose4_kernel<<<tg, tb>>>(Wq, Wk, Wv, Wo, w16);

    cudaFuncSetAttribute(gemm_fp16, cudaFuncAttributeMaxDynamicSharedMemorySize, GSMEM);
    // fused QKV: N = 3072 (Wq|Wk|Wv transposed are contiguous in w16)
    gemm_fp16<<<dim3(24, 32), 256, GSMEM>>>(x16, w16, bq, bk, bv, qkv16, 3072, 1);

    dim3 prep_grid(N_TOK / 8, HEADS), prep_blk(64, 8);
    prep_kernel<<<prep_grid, prep_blk>>>(qkv16, J, lam, qc, kc, vt);

    cudaFuncSetAttribute(flash16_kernel, cudaFuncAttributeMaxDynamicSharedMemorySize,
                         FL16_SMEM);
    dim3 fl_grid(SEQ / 256, BH);
    flash16_kernel<<<fl_grid, 512, FL16_SMEM>>>(qc, kc, vt, o16);

    gemm_fp16<<<dim3(8, 32), 256, GSMEM>>>(o16, wo16, bo, bo, bo, out, 1024, 0);
}

// round 12
// speedup vs baseline: 1.1109x; 1.1109x over previous
#include <cuda_runtime.h>
#include <cuda_fp16.h>
#include <math.h>
#include <stdint.h>

// ---------------------------------------------------------------------------
// QBNN attention, all-fp16 tensor-core pipeline. B=2, S=2048, E=1024, H=16, hd=64.
//  0) convert: x -> fp16 ; W* -> transposed fp16 (fused 4-way)
//  1) gemm_fp16 fused: QKV = x@[Wq|Wk|Wv] + b  (one launch, N=3072)
//  2) prep (R9-proven): Qcat(log2e)/Kcat fp16, Vt fp16
//  3) flash16 (R9-proven): 128-row q-tiles, 8 warps, log2-domain softmax
//  4) gemm_fp16: out = O@Wo + bo (fp32 out)
// ---------------------------------------------------------------------------

#define N_TOK   4096
#define EMB     1024
#define HEADS   16
#define HD      64
#define SEQ     2048
#define BH      32
#define LOG2E   1.4426950408889634f

// fp16 scratch arena
#define HX     0
#define HW     (HX    + N_TOK*EMB)           // 4 transposed weights
#define HQKV   (HW    + 4*EMB*EMB)           // [4096][3072]
#define HQC    (HQKV  + N_TOK*3*EMB)
#define HKC    (HQC   + BH*SEQ*128)
#define HVT    (HKC   + BH*SEQ*128)
#define HO     (HVT   + BH*64*SEQ)
#define HTOTAL (HO    + N_TOK*EMB)
__device__ __half g_hscratch[HTOTAL];

// ---------------------------------------------------------------------------
// convert: fp32 -> fp16 elementwise
// ---------------------------------------------------------------------------
__global__ __launch_bounds__(256)
void convert_kernel(const float* __restrict__ src, __half* __restrict__ dst, int n4)
{
    int i = blockIdx.x * blockDim.x + threadIdx.x;
    if (i >= n4) return;
    float4 v = ((const float4*)src)[i];
    __half2 h0 = __floats2half2_rn(v.x, v.y);
    __half2 h1 = __floats2half2_rn(v.z, v.w);
    uint2 w;
    w.x = *(uint32_t*)&h0;
    w.y = *(uint32_t*)&h1;
    ((uint2*)dst)[i] = w;
}

// ---------------------------------------------------------------------------
// fused transpose+convert of all 4 weights: W[k][n] fp32 -> Wt[n][k] fp16
// ---------------------------------------------------------------------------
__global__ __launch_bounds__(256)
void transpose4_kernel(const float* __restrict__ W0, const float* __restrict__ W1,
                       const float* __restrict__ W2, const float* __restrict__ W3,
                       __half* __restrict__ Tbase)
{
    __shared__ float tile[32][33];
    int z  = blockIdx.z;
    const float* W = (z == 0) ? W0 : (z == 1) ? W1 : (z == 2) ? W2 : W3;
    __half* T = Tbase + (size_t)z * EMB * EMB;

    int k0 = blockIdx.y * 32;
    int n0 = blockIdx.x * 32;
    int tx = threadIdx.x & 31;
    int ty = threadIdx.x >> 5;
#pragma unroll
    for (int j = 0; j < 4; j++)
        tile[ty + j * 8][tx] = W[(size_t)(k0 + ty + j * 8) * EMB + n0 + tx];
    __syncthreads();
#pragma unroll
    for (int j = 0; j < 4; j++) {
        int n = ty + j * 8;
        T[(size_t)(n0 + n) * EMB + k0 + tx] = __float2half(tile[tx][n]);
    }
}

// ---------------------------------------------------------------------------
// helpers
// ---------------------------------------------------------------------------
#define MMA16816H(d, a0, a1, a2, a3, b0, b1)                                 \
    asm volatile(                                                            \
        "mma.sync.aligned.m16n8k16.row.col.f32.f16.f16.f32 "                 \
        "{%0,%1,%2,%3}, {%4,%5,%6,%7}, {%8,%9}, {%0,%1,%2,%3};"              \
        : "+f"(d[0]), "+f"(d[1]), "+f"(d[2]), "+f"(d[3])                     \
        : "r"(a0), "r"(a1), "r"(a2), "r"(a3), "r"(b0), "r"(b1))

#define LDSM_X4(r0, r1, r2, r3, addr)                                        \
    asm volatile("ldmatrix.sync.aligned.m8n8.x4.shared.b16 {%0,%1,%2,%3}, [%4];" \
        : "=r"(r0), "=r"(r1), "=r"(r2), "=r"(r3) : "r"(addr))

__device__ __forceinline__ void cp16s(uint32_t smem_dst, const void* gmem_src)
{
    asm volatile("cp.async.cg.shared.global [%0], [%1], 16;"
                 :: "r"(smem_dst), "l"(gmem_src));
}

__device__ __forceinline__ uint32_t h2exp2(uint32_t x)
{
    uint32_t r;
    asm("ex2.approx.f16x2 %0, %1;" : "=r"(r) : "r"(x));
    return r;
}

__device__ __forceinline__ float tanh_fast(float x)
{
    float r;
    asm("tanh.approx.f32 %0, %1;" : "=f"(r) : "f"(x));
    return r;
}

// ---------------------------------------------------------------------------
// Single-pass fp16 tensor-core GEMM, fused-N capable.
// ---------------------------------------------------------------------------
#define GSTAGE  32768
#define GSMEM   (3 * GSTAGE)

__global__ __launch_bounds__(256, 2)
void gemm_fp16(const __half* __restrict__ A, const __half* __restrict__ Bt,
               const float* __restrict__ b0p, const float* __restrict__ b1p,
               const float* __restrict__ b2p,
               void* __restrict__ Cout, int outN, int half_out)
{
    extern __shared__ __align__(1024) char smem[];
    const int K = 1024;
    uint32_t sbase;
    asm("{ .reg .u64 t; cvta.to.shared.u64 t, %1; cvt.u32.u64 %0, t; }"
        : "=r"(sbase) : "l"(smem));

    int tid  = threadIdx.x;
    int warp = tid >> 5;
    int lane = tid & 31;
    int wm   = warp & 1;
    int wn   = warp >> 1;
    int m0   = blockIdx.y * 128;
    int n0   = blockIdx.x * 128;

    int sec = n0 >> 10;
    const float* bias = (sec == 0) ? b0p : (sec == 1) ? b1p : b2p;
    int nloc = n0 & 1023;

    float acc[4][4][4];
#pragma unroll
    for (int mi = 0; mi < 4; mi++)
#pragma unroll
        for (int nj = 0; nj < 4; nj++)
#pragma unroll
            for (int t = 0; t < 4; t++) acc[mi][nj][t] = 0.f;

    auto issue = [&](int chunk, int stg) {
        int k0 = chunk << 6;
        const __half* Ap = A  + (size_t)m0 * K + k0;
        const __half* Bp = Bt + (size_t)n0 * K + k0;
        uint32_t aBuf = sbase + stg * GSTAGE;
        uint32_t bBuf = aBuf + 16384;
#pragma unroll
        for (int i = 0; i < 4; i++) {
            int idx = tid + i * 256;
            int r   = idx >> 3;
            int c   = idx & 7;
            uint32_t sw = (uint32_t)(r << 7) | ((uint32_t)(c ^ (r & 7)) << 4);
            cp16s(aBuf + sw, Ap + (size_t)r * K + c * 8);
            cp16s(bBuf + sw, Bp + (size_t)r * K + c * 8);
        }
        asm volatile("cp.async.commit_group;");
    };

    issue(0, 0);
    issue(1, 1);

    int lm  = lane >> 3;
    int lr  = lane & 7;

    for (int t = 0; t < 16; t++) {
        int stg = t % 3;
        if (t < 15) asm volatile("cp.async.wait_group 1;");
        else        asm volatile("cp.async.wait_group 0;");
        __syncthreads();

        uint32_t aBuf = sbase + stg * GSTAGE;
        uint32_t bBuf = aBuf + 16384;

#pragma unroll
        for (int kk = 0; kk < 64; kk += 16) {
            int kc = kk >> 3;
            uint32_t af[4][4];
#pragma unroll
            for (int mi = 0; mi < 4; mi++) {
                int row = wm * 64 + mi * 16 + (lm & 1) * 8 + lr;
                int ch  = kc + (lm >> 1);
                uint32_t ad = aBuf + (uint32_t)(row << 7) + ((uint32_t)(ch ^ (row & 7)) << 4);
                LDSM_X4(af[mi][0], af[mi][1], af[mi][2], af[mi][3], ad);
            }
            uint32_t bf_[4][2];
#pragma unroll
            for (int njp = 0; njp < 2; njp++) {
                int row = wn * 32 + njp * 16 + (lm >> 1) * 8 + lr;
                int ch  = kc + (lm & 1);
                uint32_t bd = bBuf + (uint32_t)(row << 7) + ((uint32_t)(ch ^ (row & 7)) << 4);
                LDSM_X4(bf_[njp * 2][0], bf_[njp * 2][1],
                        bf_[njp * 2 + 1][0], bf_[njp * 2 + 1][1], bd);
            }
#pragma unroll
            for (int mi = 0; mi < 4; mi++)
#pragma unroll
                for (int nj = 0; nj < 4; nj++)
                    MMA16816H(acc[mi][nj], af[mi][0], af[mi][1], af[mi][2], af[mi][3],
                              bf_[nj][0], bf_[nj][1]);
        }

        if (t + 2 < 16) issue(t + 2, (t + 2) % 3);
    }

    int g  = lane >> 2;
    int tq = lane & 3;
#pragma unroll
    for (int mi = 0; mi < 4; mi++) {
        size_t r0 = (size_t)(m0 + wm * 64 + mi * 16 + g);
        size_t r1 = r0 + 8;
#pragma unroll
        for (int nj = 0; nj < 4; nj++) {
            int cl = wn * 32 + nj * 8 + tq * 2;
            float b0 = bias[nloc + cl], b1 = bias[nloc + cl + 1];
            int c  = n0 + cl;
            float v00 = acc[mi][nj][0] + b0, v01 = acc[mi][nj][1] + b1;
            float v10 = acc[mi][nj][2] + b0, v11 = acc[mi][nj][3] + b1;
            if (half_out) {
                __half* C = (__half*)Cout;
                *(__half2*)&C[r0 * outN + c] = __floats2half2_rn(v00, v01);
                *(__half2*)&C[r1 * outN + c] = __floats2half2_rn(v10, v11);
            } else {
                float* C = (float*)Cout;
                *(float2*)&C[r0 * outN + c] = make_float2(v00, v01);
                *(float2*)&C[r1 * outN + c] = make_float2(v10, v11);
            }
        }
    }
}

// ---------------------------------------------------------------------------
// prep (R9-proven structure): reads fused QKV [tok][3072].
// ---------------------------------------------------------------------------
__global__ __launch_bounds__(512)
void prep_kernel(const __half* __restrict__ QKV, const float* __restrict__ J,
                 const float* __restrict__ lamp,
                 __half* __restrict__ Qc, __half* __restrict__ Kc,
                 __half* __restrict__ Vt)
{
    __shared__ float Js[4096];
    __shared__ float qn[8][64];

    int h   = blockIdx.y;
    int d   = threadIdx.x;
    int ty  = threadIdx.y;
    int tid = ty * 64 + d;

    for (int i = tid; i < 4096; i += 512) Js[i] = J[h * 4096 + i];

    int tok = blockIdx.x * 8 + ty;
    int b   = tok >> 11;
    int s   = tok & 2047;
    int bh  = (b << 4) + h;

    const __half* row = QKV + (size_t)tok * 3072 + h * HD + d;
    float q = __half2float(row[0]);
    float k = __half2float(row[1024]);
    __half v = row[2048];
    qn[ty][d] = tanh_fast(q);
    __syncthreads();

    float accv = 0.f;
#pragma unroll 8
    for (int dd = 0; dd < 64; dd++) accv += qn[ty][dd] * Js[dd * 64 + d];

    float lam = lamp[0];
    size_t base = (size_t)bh * SEQ + s;
    Qc[base * 128 + d]      = __float2half(q * 0.125f * LOG2E);
    Qc[base * 128 + 64 + d] = __float2half(lam * accv * LOG2E);
    Kc[base * 128 + d]      = __float2half(k);
    Kc[base * 128 + 64 + d] = __float2half(tanh_fast(k));
    Vt[((size_t)bh * 64 + d) * SEQ + s] = v;
}

// ---------------------------------------------------------------------------
// flash16 (R9-proven): 128-row q-tiles, 8 warps, 3-stage KV, log2 softmax.
// ---------------------------------------------------------------------------
#define FLQ_BYTES  32768
#define FLSTAGE    24576
#define FL16_SMEM  (FLQ_BYTES + 3 * FLSTAGE)

__global__ __launch_bounds__(256, 1)
void flash16_kernel(const __half* __restrict__ Qc, const __half* __restrict__ Kc,
                    const __half* __restrict__ Vt, __half* __restrict__ O)
{
    extern __shared__ __align__(1024) char smem[];
    uint32_t sbase;
    asm("{ .reg .u64 t; cvta.to.shared.u64 t, %1; cvt.u32.u64 %0, t; }"
        : "=r"(sbase) : "l"(smem));

    int tid  = threadIdx.x;
    int w    = tid >> 5;
    int lane = tid & 31;
    int lm   = lane >> 3;
    int lr   = lane & 7;
    int g    = lane >> 2;
    int tq   = lane & 3;

    int bh    = blockIdx.y;
    int b     = bh >> 4;
    int h     = bh & 15;
    int qtile = (int)gridDim.x - 1 - (int)blockIdx.x;
    int qt0   = qtile * 128;
    int nkt   = 2 * qtile + 2;

    const __half* Qg = Qc + ((size_t)bh * SEQ + qt0) * 128;
#pragma unroll
    for (int i = 0; i < 8; i++) {
        int idx = tid + i * 256;
        int r   = idx >> 4;
        int ch  = idx & 15;
        uint32_t dst = sbase + (uint32_t)(ch >> 3) * 16384
                     + (uint32_t)(r << 7) + ((uint32_t)((ch & 7) ^ (r & 7)) << 4);
        cp16s(dst, Qg + (size_t)r * 128 + ch * 8);
    }
    asm volatile("cp.async.commit_group;");

    auto issueKV = [&](int kt, int s) {
        uint32_t kb = sbase + FLQ_BYTES + (uint32_t)s * FLSTAGE;
        uint32_t vb = kb + 16384;
        const __half* Kg = Kc + ((size_t)bh * SEQ + kt * 64) * 128;
        const __half* Vg = Vt + (size_t)bh * 64 * SEQ + kt * 64;
#pragma unroll
        for (int i = 0; i < 4; i++) {
            int idx = tid + i * 256;
            int r   = idx >> 4;
            int ch  = idx & 15;
            uint32_t dst = kb + (uint32_t)(ch >> 3) * 8192
                         + (uint32_t)(r << 7) + ((uint32_t)((ch & 7) ^ (r & 7)) << 4);
            cp16s(dst, Kg + (size_t)r * 128 + ch * 8);
        }
#pragma unroll
        for (int i = 0; i < 2; i++) {
            int idx = tid + i * 256;
            int r   = idx >> 3;
            int c   = idx & 7;
            uint32_t dst = vb + (uint32_t)(r << 7) + ((uint32_t)(c ^ (r & 7)) << 4);
            cp16s(dst, Vg + (size_t)r * SEQ + c * 8);
        }
        asm volatile("cp.async.commit_group;");
    };

    issueKV(0, 0);
    issueKV(1, 1);

    asm volatile("cp.async.wait_group 2;");
    __syncthreads();

    uint32_t qf[8][4];
#pragma unroll
    for (int ks = 0; ks < 8; ks++) {
        int half = ks >> 2;
        int kc   = (ks & 3) * 2 + (lm >> 1);
        int row  = w * 16 + (lm & 1) * 8 + lr;
        uint32_t ad = sbase + (uint32_t)half * 16384
                    + (uint32_t)(row << 7) + ((uint32_t)(kc ^ (row & 7)) << 4);
        LDSM_X4(qf[ks][0], qf[ks][1], qf[ks][2], qf[ks][3], ad);
    }

    float oacc[8][4];
#pragma unroll
    for (int nt = 0; nt < 8; nt++)
#pragma unroll
        for (int t = 0; t < 4; t++) oacc[nt][t] = 0.f;
    float mrow[2] = {-1e30f, -1e30f};
    float lrow[2] = {0.f, 0.f};

    int qrow0 = qt0 + w * 16;
    int r0g   = qrow0 + g;

    for (int kt = 0; kt < nkt; kt++) {
        int s_ = kt % 3;
        if (kt + 1 < nkt) asm volatile("cp.async.wait_group 1;");
        else              asm volatile("cp.async.wait_group 0;");
        __syncthreads();

        if (kt + 2 < nkt) issueKV(kt + 2, (kt + 2) % 3);

        uint32_t kb = sbase + FLQ_BYTES + (uint32_t)s_ * FLSTAGE;
        uint32_t vb = kb + 16384;

        float sacc[8][4];
#pragma unroll
        for (int nt = 0; nt < 8; nt++)
#pragma unroll
            for (int t = 0; t < 4; t++) sacc[nt][t] = 0.f;

#pragma unroll
        for (int ks = 0; ks < 8; ks++) {
            int half = ks >> 2;
            int kc   = (ks & 3) * 2 + (lm & 1);
            uint32_t kf[8][2];
#pragma unroll
            for (int nb = 0; nb < 4; nb++) {
                int row = nb * 16 + (lm >> 1) * 8 + lr;
                uint32_t ad = kb + (uint32_t)half * 8192
                            + (uint32_t)(row << 7) + ((uint32_t)(kc ^ (row & 7)) << 4);
                LDSM_X4(kf[nb * 2][0], kf[nb * 2][1],
                        kf[nb * 2 + 1][0], kf[nb * 2 + 1][1], ad);
            }
#pragma unroll
            for (int nt = 0; nt < 8; nt++)
                MMA16816H(sacc[nt], qf[ks][0], qf[ks][1], qf[ks][2], qf[ks][3],
                          kf[nt][0], kf[nt][1]);
        }

        if (kt * 64 + 63 > qrow0) {
#pragma unroll
            for (int nt = 0; nt < 8; nt++) {
                int c0 = kt * 64 + nt * 8 + 2 * tq;
                if (c0     > r0g)     sacc[nt][0] = -1e30f;
                if (c0 + 1 > r0g)     sacc[nt][1] = -1e30f;
                if (c0     > r0g + 8) sacc[nt][2] = -1e30f;
                if (c0 + 1 > r0g + 8) sacc[nt][3] = -1e30f;
            }
        }

        float tm0 = -1e30f, tm1 = -1e30f;
#pragma unroll
        for (int nt = 0; nt < 8; nt++) {
            tm0 = fmaxf(tm0, fmaxf(sacc[nt][0], sacc[nt][1]));
            tm1 = fmaxf(tm1, fmaxf(sacc[nt][2], sacc[nt][3]));
        }
        tm0 = fmaxf(tm0, __shfl_xor_sync(0xffffffffu, tm0, 1));
        tm0 = fmaxf(tm0, __shfl_xor_sync(0xffffffffu, tm0, 2));
        tm1 = fmaxf(tm1, __shfl_xor_sync(0xffffffffu, tm1, 1));
        tm1 = fmaxf(tm1, __shfl_xor_sync(0xffffffffu, tm1, 2));

        float mnew0 = fmaxf(mrow[0], tm0);
        float mnew1 = fmaxf(mrow[1], tm1);
        float corr0 = exp2f(mrow[0] - mnew0);
        float corr1 = exp2f(mrow[1] - mnew1);
        mrow[0] = mnew0;
        mrow[1] = mnew1;
#pragma unroll
        for (int nt = 0; nt < 8; nt++) {
            oacc[nt][0] *= corr0; oacc[nt][1] *= corr0;
            oacc[nt][2] *= corr1; oacc[nt][3] *= corr1;
        }

        uint32_t pf[4][4];
        float ps0 = 0.f, ps1 = 0.f;
#pragma unroll
        for (int nt = 0; nt < 8; nt++) {
            __half2 d0 = __floats2half2_rn(sacc[nt][0] - mnew0, sacc[nt][1] - mnew0);
            __half2 d1 = __floats2half2_rn(sacc[nt][2] - mnew1, sacc[nt][3] - mnew1);
            uint32_t p0 = h2exp2(*(uint32_t*)&d0);
            uint32_t p1 = h2exp2(*(uint32_t*)&d1);
            float2 f0 = __half22float2(*(__half2*)&p0);
            float2 f1 = __half22float2(*(__half2*)&p1);
            ps0 += f0.x + f0.y;
            ps1 += f1.x + f1.y;
            pf[nt >> 1][(nt & 1) * 2]     = p0;
            pf[nt >> 1][(nt & 1) * 2 + 1] = p1;
        }
        ps0 += __shfl_xor_sync(0xffffffffu, ps0, 1);
        ps0 += __shfl_xor_sync(0xffffffffu, ps0, 2);
        ps1 += __shfl_xor_sync(0xffffffffu, ps1, 1);
        ps1 += __shfl_xor_sync(0xffffffffu, ps1, 2);
        lrow[0] = lrow[0] * corr0 + ps0;
        lrow[1] = lrow[1] * corr1 + ps1;

#pragma unroll
        for (int kc16 = 0; kc16 < 4; kc16++) {
            int kc = kc16 * 2 + (lm & 1);
            uint32_t vf[8][2];
#pragma unroll
            for (int nb = 0; nb < 4; nb++) {
                int row = nb * 16 + (lm >> 1) * 8 + lr;
                uint32_t ad = vb + (uint32_t)(row << 7)
                            + ((uint32_t)(kc ^ (row & 7)) << 4);
                LDSM_X4(vf[nb * 2][0], vf[nb * 2][1],
                        vf[nb * 2 + 1][0], vf[nb * 2 + 1][1], ad);
            }
#pragma unroll
            for (int nt = 0; nt < 8; nt++)
                MMA16816H(oacc[nt], pf[kc16][0], pf[kc16][1], pf[kc16][2], pf[kc16][3],
                          vf[nt][0], vf[nt][1]);
        }
    }

    float inv0 = 1.0f / lrow[0];
    float inv1 = 1.0f / lrow[1];
    size_t rt0 = (size_t)(b * SEQ + qt0 + w * 16 + g);
    __half* O0 = O + rt0 * EMB + h * 64;
    __half* O1 = O0 + (size_t)8 * EMB;
#pragma unroll
    for (int nt = 0; nt < 8; nt++) {
        int c = nt * 8 + 2 * tq;
        *(__half2*)&O0[c] = __floats2half2_rn(oacc[nt][0] * inv0, oacc[nt][1] * inv0);
        *(__half2*)&O1[c] = __floats2half2_rn(oacc[nt][2] * inv1, oacc[nt][3] * inv1);
    }
}

// ---------------------------------------------------------------------------
// launch
// ---------------------------------------------------------------------------
extern "C" void kernel_launch(void* const* d_in, const int* in_sizes, int n_in,
                              void* d_out, int out_size)
{
    const float* x   = (const float*)d_in[0];
    const float* Wq  = (const float*)d_in[1];
    const float* bq  = (const float*)d_in[2];
    const float* Wk  = (const float*)d_in[3];
    const float* bk  = (const float*)d_in[4];
    const float* Wv  = (const float*)d_in[5];
    const float* bv  = (const float*)d_in[6];
    const float* Wo  = (const float*)d_in[7];
    const float* bo  = (const float*)d_in[8];
    const float* J   = (const float*)d_in[9];
    const float* lam = (const float*)d_in[10];
    float* out = (float*)d_out;

    void* p = nullptr;
    cudaGetSymbolAddress(&p, g_hscratch);
    __half* hs    = (__half*)p;
    __half* x16   = hs + HX;
    __half* w16   = hs + HW;
    __half* qkv16 = hs + HQKV;
    __half* qc    = hs + HQC;
    __half* kc    = hs + HKC;
    __half* vt    = hs + HVT;
    __half* o16   = hs + HO;

    const int WSZ = EMB * EMB;
    __half* wo16 = w16 + 3 * WSZ;

    convert_kernel<<<(N_TOK * EMB / 4 + 255) / 256, 256>>>(x, x16, N_TOK * EMB / 4);
    dim3 tg(32, 32, 4), tb(256);
    transpose4_kernel<<<tg, tb>>>(Wq, Wk, Wv, Wo, w16);

    cudaFuncSetAttribute(gemm_fp16, cudaFuncAttributeMaxDynamicSharedMemorySize, GSMEM);
    // fused QKV: N = 3072 (Wq|Wk|Wv transposed contiguous in w16)
    gemm_fp16<<<dim3(24, 32), 256, GSMEM>>>(x16, w16, bq, bk, bv, qkv16, 3072, 1);

    dim3 prep_grid(N_TOK / 8, HEADS), prep_blk(64, 8);
    prep_kernel<<<prep_grid, prep_blk>>>(qkv16, J, lam, qc, kc, vt);

    cudaFuncSetAttribute(flash16_kernel, cudaFuncAttributeMaxDynamicSharedMemorySize,
                         FL16_SMEM);
    dim3 fl_grid(SEQ / 128, BH);
    flash16_kernel<<<fl_grid, 256, FL16_SMEM>>>(qc, kc, vt, o16);

    gemm_fp16<<<dim3(8, 32), 256, GSMEM>>>(o16, wo16, bo, bo, bo, out, 1024, 0);
}

// round 13
// speedup vs baseline: 1.2135x; 1.0923x over previous
#include <cuda_runtime.h>
#include <cuda_fp16.h>
#include <math.h>
#include <stdint.h>

// ---------------------------------------------------------------------------
// QBNN attention, all-fp16 tensor-core pipeline. B=2, S=2048, E=1024, H=16, hd=64.
//  0) convert: x -> fp16 ; W* -> transposed fp16 (fused 4-way)
//  1) gemm_fp16 fused: QKV = x@[Wq|Wk|Wv] + b  (one launch, N=3072)
//  2) prep: Qcat(log2e)/Kcat fp16 only (V stays in QKV; no scatter)
//  3) flash16: 128-row q-tiles, 8 warps, V direct from QKV via ldmatrix.trans
//  4) gemm_fp16: out = O@Wo + bo (fp32 out)
// ---------------------------------------------------------------------------

#define N_TOK   4096
#define EMB     1024
#define HEADS   16
#define HD      64
#define SEQ     2048
#define BH      32
#define LOG2E   1.4426950408889634f

// fp16 scratch arena
#define HX     0
#define HW     (HX    + N_TOK*EMB)           // 4 transposed weights
#define HQKV   (HW    + 4*EMB*EMB)           // [4096][3072]
#define HQC    (HQKV  + N_TOK*3*EMB)
#define HKC    (HQC   + BH*SEQ*128)
#define HO     (HKC   + BH*SEQ*128)
#define HTOTAL (HO    + N_TOK*EMB)
__device__ __half g_hscratch[HTOTAL];

// ---------------------------------------------------------------------------
// convert: fp32 -> fp16 elementwise
// ---------------------------------------------------------------------------
__global__ __launch_bounds__(256)
void convert_kernel(const float* __restrict__ src, __half* __restrict__ dst, int n4)
{
    int i = blockIdx.x * blockDim.x + threadIdx.x;
    if (i >= n4) return;
    float4 v = ((const float4*)src)[i];
    __half2 h0 = __floats2half2_rn(v.x, v.y);
    __half2 h1 = __floats2half2_rn(v.z, v.w);
    uint2 w;
    w.x = *(uint32_t*)&h0;
    w.y = *(uint32_t*)&h1;
    ((uint2*)dst)[i] = w;
}

// ---------------------------------------------------------------------------
// fused transpose+convert of all 4 weights: W[k][n] fp32 -> Wt[n][k] fp16
// ---------------------------------------------------------------------------
__global__ __launch_bounds__(256)
void transpose4_kernel(const float* __restrict__ W0, const float* __restrict__ W1,
                       const float* __restrict__ W2, const float* __restrict__ W3,
                       __half* __restrict__ Tbase)
{
    __shared__ float tile[32][33];
    int z  = blockIdx.z;
    const float* W = (z == 0) ? W0 : (z == 1) ? W1 : (z == 2) ? W2 : W3;
    __half* T = Tbase + (size_t)z * EMB * EMB;

    int k0 = blockIdx.y * 32;
    int n0 = blockIdx.x * 32;
    int tx = threadIdx.x & 31;
    int ty = threadIdx.x >> 5;
#pragma unroll
    for (int j = 0; j < 4; j++)
        tile[ty + j * 8][tx] = W[(size_t)(k0 + ty + j * 8) * EMB + n0 + tx];
    __syncthreads();
#pragma unroll
    for (int j = 0; j < 4; j++) {
        int n = ty + j * 8;
        T[(size_t)(n0 + n) * EMB + k0 + tx] = __float2half(tile[tx][n]);
    }
}

// ---------------------------------------------------------------------------
// helpers
// ---------------------------------------------------------------------------
#define MMA16816H(d, a0, a1, a2, a3, b0, b1)                                 \
    asm volatile(                                                            \
        "mma.sync.aligned.m16n8k16.row.col.f32.f16.f16.f32 "                 \
        "{%0,%1,%2,%3}, {%4,%5,%6,%7}, {%8,%9}, {%0,%1,%2,%3};"              \
        : "+f"(d[0]), "+f"(d[1]), "+f"(d[2]), "+f"(d[3])                     \
        : "r"(a0), "r"(a1), "r"(a2), "r"(a3), "r"(b0), "r"(b1))

#define LDSM_X4(r0, r1, r2, r3, addr)                                        \
    asm volatile("ldmatrix.sync.aligned.m8n8.x4.shared.b16 {%0,%1,%2,%3}, [%4];" \
        : "=r"(r0), "=r"(r1), "=r"(r2), "=r"(r3) : "r"(addr))

#define LDSM_X4_T(r0, r1, r2, r3, addr)                                      \
    asm volatile("ldmatrix.sync.aligned.m8n8.x4.trans.shared.b16 {%0,%1,%2,%3}, [%4];" \
        : "=r"(r0), "=r"(r1), "=r"(r2), "=r"(r3) : "r"(addr))

__device__ __forceinline__ void cp16s(uint32_t smem_dst, const void* gmem_src)
{
    asm volatile("cp.async.cg.shared.global [%0], [%1], 16;"
                 :: "r"(smem_dst), "l"(gmem_src));
}

__device__ __forceinline__ uint32_t h2exp2(uint32_t x)
{
    uint32_t r;
    asm("ex2.approx.f16x2 %0, %1;" : "=r"(r) : "r"(x));
    return r;
}

__device__ __forceinline__ float tanh_fast(float x)
{
    float r;
    asm("tanh.approx.f32 %0, %1;" : "=f"(r) : "f"(x));
    return r;
}

// ---------------------------------------------------------------------------
// Single-pass fp16 tensor-core GEMM, fused-N capable.
// ---------------------------------------------------------------------------
#define GSTAGE  32768
#define GSMEM   (3 * GSTAGE)

__global__ __launch_bounds__(256, 2)
void gemm_fp16(const __half* __restrict__ A, const __half* __restrict__ Bt,
               const float* __restrict__ b0p, const float* __restrict__ b1p,
               const float* __restrict__ b2p,
               void* __restrict__ Cout, int outN, int half_out)
{
    extern __shared__ __align__(1024) char smem[];
    const int K = 1024;
    uint32_t sbase;
    asm("{ .reg .u64 t; cvta.to.shared.u64 t, %1; cvt.u32.u64 %0, t; }"
        : "=r"(sbase) : "l"(smem));

    int tid  = threadIdx.x;
    int warp = tid >> 5;
    int lane = tid & 31;
    int wm   = warp & 1;
    int wn   = warp >> 1;
    int m0   = blockIdx.y * 128;
    int n0   = blockIdx.x * 128;

    int sec = n0 >> 10;
    const float* bias = (sec == 0) ? b0p : (sec == 1) ? b1p : b2p;
    int nloc = n0 & 1023;

    float acc[4][4][4];
#pragma unroll
    for (int mi = 0; mi < 4; mi++)
#pragma unroll
        for (int nj = 0; nj < 4; nj++)
#pragma unroll
            for (int t = 0; t < 4; t++) acc[mi][nj][t] = 0.f;

    auto issue = [&](int chunk, int stg) {
        int k0 = chunk << 6;
        const __half* Ap = A  + (size_t)m0 * K + k0;
        const __half* Bp = Bt + (size_t)n0 * K + k0;
        uint32_t aBuf = sbase + stg * GSTAGE;
        uint32_t bBuf = aBuf + 16384;
#pragma unroll
        for (int i = 0; i < 4; i++) {
            int idx = tid + i * 256;
            int r   = idx >> 3;
            int c   = idx & 7;
            uint32_t sw = (uint32_t)(r << 7) | ((uint32_t)(c ^ (r & 7)) << 4);
            cp16s(aBuf + sw, Ap + (size_t)r * K + c * 8);
            cp16s(bBuf + sw, Bp + (size_t)r * K + c * 8);
        }
        asm volatile("cp.async.commit_group;");
    };

    issue(0, 0);
    issue(1, 1);

    int lm  = lane >> 3;
    int lr  = lane & 7;

    for (int t = 0; t < 16; t++) {
        int stg = t % 3;
        if (t < 15) asm volatile("cp.async.wait_group 1;");
        else        asm volatile("cp.async.wait_group 0;");
        __syncthreads();

        uint32_t aBuf = sbase + stg * GSTAGE;
        uint32_t bBuf = aBuf + 16384;

#pragma unroll
        for (int kk = 0; kk < 64; kk += 16) {
            int kc = kk >> 3;
            uint32_t af[4][4];
#pragma unroll
            for (int mi = 0; mi < 4; mi++) {
                int row = wm * 64 + mi * 16 + (lm & 1) * 8 + lr;
                int ch  = kc + (lm >> 1);
                uint32_t ad = aBuf + (uint32_t)(row << 7) + ((uint32_t)(ch ^ (row & 7)) << 4);
                LDSM_X4(af[mi][0], af[mi][1], af[mi][2], af[mi][3], ad);
            }
            uint32_t bf_[4][2];
#pragma unroll
            for (int njp = 0; njp < 2; njp++) {
                int row = wn * 32 + njp * 16 + (lm >> 1) * 8 + lr;
                int ch  = kc + (lm & 1);
                uint32_t bd = bBuf + (uint32_t)(row << 7) + ((uint32_t)(ch ^ (row & 7)) << 4);
                LDSM_X4(bf_[njp * 2][0], bf_[njp * 2][1],
                        bf_[njp * 2 + 1][0], bf_[njp * 2 + 1][1], bd);
            }
#pragma unroll
            for (int mi = 0; mi < 4; mi++)
#pragma unroll
                for (int nj = 0; nj < 4; nj++)
                    MMA16816H(acc[mi][nj], af[mi][0], af[mi][1], af[mi][2], af[mi][3],
                              bf_[nj][0], bf_[nj][1]);
        }

        if (t + 2 < 16) issue(t + 2, (t + 2) % 3);
    }

    int g  = lane >> 2;
    int tq = lane & 3;
#pragma unroll
    for (int mi = 0; mi < 4; mi++) {
        size_t r0 = (size_t)(m0 + wm * 64 + mi * 16 + g);
        size_t r1 = r0 + 8;
#pragma unroll
        for (int nj = 0; nj < 4; nj++) {
            int cl = wn * 32 + nj * 8 + tq * 2;
            float b0 = bias[nloc + cl], b1 = bias[nloc + cl + 1];
            int c  = n0 + cl;
            float v00 = acc[mi][nj][0] + b0, v01 = acc[mi][nj][1] + b1;
            float v10 = acc[mi][nj][2] + b0, v11 = acc[mi][nj][3] + b1;
            if (half_out) {
                __half* C = (__half*)Cout;
                *(__half2*)&C[r0 * outN + c] = __floats2half2_rn(v00, v01);
                *(__half2*)&C[r1 * outN + c] = __floats2half2_rn(v10, v11);
            } else {
                float* C = (float*)Cout;
                *(float2*)&C[r0 * outN + c] = make_float2(v00, v01);
                *(float2*)&C[r1 * outN + c] = make_float2(v10, v11);
            }
        }
    }
}

// ---------------------------------------------------------------------------
// prep: Qcat/Kcat only (V untouched — flash reads it from QKV directly).
// ---------------------------------------------------------------------------
__global__ __launch_bounds__(512)
void prep_kernel(const __half* __restrict__ QKV, const float* __restrict__ J,
                 const float* __restrict__ lamp,
                 __half* __restrict__ Qc, __half* __restrict__ Kc)
{
    __shared__ float Js[4096];
    __shared__ float qn[8][64];

    int h   = blockIdx.y;
    int d   = threadIdx.x;
    int ty  = threadIdx.y;
    int tid = ty * 64 + d;

    for (int i = tid; i < 4096; i += 512) Js[i] = J[h * 4096 + i];

    int tok = blockIdx.x * 8 + ty;
    int b   = tok >> 11;
    int s   = tok & 2047;
    int bh  = (b << 4) + h;

    const __half* row = QKV + (size_t)tok * 3072 + h * HD + d;
    float q = __half2float(row[0]);
    float k = __half2float(row[1024]);
    qn[ty][d] = tanh_fast(q);
    __syncthreads();

    float accv = 0.f;
#pragma unroll 8
    for (int dd = 0; dd < 64; dd++) accv += qn[ty][dd] * Js[dd * 64 + d];

    float lam = lamp[0];
    size_t base = (size_t)bh * SEQ + s;
    Qc[base * 128 + d]      = __float2half(q * 0.125f * LOG2E);
    Qc[base * 128 + 64 + d] = __float2half(lam * accv * LOG2E);
    Kc[base * 128 + d]      = __float2half(k);
    Kc[base * 128 + 64 + d] = __float2half(tanh_fast(k));
}

// ---------------------------------------------------------------------------
// flash16: 128-row q-tiles, 8 warps, 3-stage KV, log2 softmax.
// V tile loaded row-major [s][dv] from QKV; B fragments via ldmatrix.trans.
// ---------------------------------------------------------------------------
#define FLQ_BYTES  32768
#define FLSTAGE    24576
#define FL16_SMEM  (FLQ_BYTES + 3 * FLSTAGE)

__global__ __launch_bounds__(256, 1)
void flash16_kernel(const __half* __restrict__ Qc, const __half* __restrict__ Kc,
                    const __half* __restrict__ QKV, __half* __restrict__ O)
{
    extern __shared__ __align__(1024) char smem[];
    uint32_t sbase;
    asm("{ .reg .u64 t; cvta.to.shared.u64 t, %1; cvt.u32.u64 %0, t; }"
        : "=r"(sbase) : "l"(smem));

    int tid  = threadIdx.x;
    int w    = tid >> 5;
    int lane = tid & 31;
    int lm   = lane >> 3;
    int lr   = lane & 7;
    int g    = lane >> 2;
    int tq   = lane & 3;

    int bh    = blockIdx.y;
    int b     = bh >> 4;
    int h     = bh & 15;
    int qtile = (int)gridDim.x - 1 - (int)blockIdx.x;
    int qt0   = qtile * 128;
    int nkt   = 2 * qtile + 2;

    const __half* Qg = Qc + ((size_t)bh * SEQ + qt0) * 128;
#pragma unroll
    for (int i = 0; i < 8; i++) {
        int idx = tid + i * 256;
        int r   = idx >> 4;
        int ch  = idx & 15;
        uint32_t dst = sbase + (uint32_t)(ch >> 3) * 16384
                     + (uint32_t)(r << 7) + ((uint32_t)((ch & 7) ^ (r & 7)) << 4);
        cp16s(dst, Qg + (size_t)r * 128 + ch * 8);
    }
    asm volatile("cp.async.commit_group;");

    auto issueKV = [&](int kt, int s) {
        uint32_t kb = sbase + FLQ_BYTES + (uint32_t)s * FLSTAGE;
        uint32_t vb = kb + 16384;
        const __half* Kg = Kc + ((size_t)bh * SEQ + kt * 64) * 128;
        // V tile: rows = tokens (b*SEQ + kt*64 + s), 64 halves at V-section offset
        const __half* Vg = QKV + (size_t)(b * SEQ + kt * 64) * 3072 + 2048 + h * 64;
#pragma unroll
        for (int i = 0; i < 4; i++) {
            int idx = tid + i * 256;
            int r   = idx >> 4;
            int ch  = idx & 15;
            uint32_t dst = kb + (uint32_t)(ch >> 3) * 8192
                         + (uint32_t)(r << 7) + ((uint32_t)((ch & 7) ^ (r & 7)) << 4);
            cp16s(dst, Kg + (size_t)r * 128 + ch * 8);
        }
#pragma unroll
        for (int i = 0; i < 2; i++) {
            int idx = tid + i * 256;
            int r   = idx >> 3;          // s row 0..63
            int c   = idx & 7;           // dv chunk 0..7
            uint32_t dst = vb + (uint32_t)(r << 7) + ((uint32_t)(c ^ (r & 7)) << 4);
            cp16s(dst, Vg + (size_t)r * 3072 + c * 8);
        }
        asm volatile("cp.async.commit_group;");
    };

    issueKV(0, 0);
    issueKV(1, 1);

    asm volatile("cp.async.wait_group 2;");
    __syncthreads();

    uint32_t qf[8][4];
#pragma unroll
    for (int ks = 0; ks < 8; ks++) {
        int half = ks >> 2;
        int kc   = (ks & 3) * 2 + (lm >> 1);
        int row  = w * 16 + (lm & 1) * 8 + lr;
        uint32_t ad = sbase + (uint32_t)half * 16384
                    + (uint32_t)(row << 7) + ((uint32_t)(kc ^ (row & 7)) << 4);
        LDSM_X4(qf[ks][0], qf[ks][1], qf[ks][2], qf[ks][3], ad);
    }

    float oacc[8][4];
#pragma unroll
    for (int nt = 0; nt < 8; nt++)
#pragma unroll
        for (int t = 0; t < 4; t++) oacc[nt][t] = 0.f;
    float mrow[2] = {-1e30f, -1e30f};
    float lrow[2] = {0.f, 0.f};

    int qrow0 = qt0 + w * 16;
    int r0g   = qrow0 + g;

    for (int kt = 0; kt < nkt; kt++) {
        int s_ = kt % 3;
        if (kt + 1 < nkt) asm volatile("cp.async.wait_group 1;");
        else              asm volatile("cp.async.wait_group 0;");
        __syncthreads();

        if (kt + 2 < nkt) issueKV(kt + 2, (kt + 2) % 3);

        uint32_t kb = sbase + FLQ_BYTES + (uint32_t)s_ * FLSTAGE;
        uint32_t vb = kb + 16384;

        float sacc[8][4];
#pragma unroll
        for (int nt = 0; nt < 8; nt++)
#pragma unroll
            for (int t = 0; t < 4; t++) sacc[nt][t] = 0.f;

#pragma unroll
        for (int ks = 0; ks < 8; ks++) {
            int half = ks >> 2;
            int kc   = (ks & 3) * 2 + (lm & 1);
            uint32_t kf[8][2];
#pragma unroll
            for (int nb = 0; nb < 4; nb++) {
                int row = nb * 16 + (lm >> 1) * 8 + lr;
                uint32_t ad = kb + (uint32_t)half * 8192
                            + (uint32_t)(row << 7) + ((uint32_t)(kc ^ (row & 7)) << 4);
                LDSM_X4(kf[nb * 2][0], kf[nb * 2][1],
                        kf[nb * 2 + 1][0], kf[nb * 2 + 1][1], ad);
            }
#pragma unroll
            for (int nt = 0; nt < 8; nt++)
                MMA16816H(sacc[nt], qf[ks][0], qf[ks][1], qf[ks][2], qf[ks][3],
                          kf[nt][0], kf[nt][1]);
        }

        if (kt * 64 + 63 > qrow0) {
#pragma unroll
            for (int nt = 0; nt < 8; nt++) {
                int c0 = kt * 64 + nt * 8 + 2 * tq;
                if (c0     > r0g)     sacc[nt][0] = -1e30f;
                if (c0 + 1 > r0g)     sacc[nt][1] = -1e30f;
                if (c0     > r0g + 8) sacc[nt][2] = -1e30f;
                if (c0 + 1 > r0g + 8) sacc[nt][3] = -1e30f;
            }
        }

        float tm0 = -1e30f, tm1 = -1e30f;
#pragma unroll
        for (int nt = 0; nt < 8; nt++) {
            tm0 = fmaxf(tm0, fmaxf(sacc[nt][0], sacc[nt][1]));
            tm1 = fmaxf(tm1, fmaxf(sacc[nt][2], sacc[nt][3]));
        }
        tm0 = fmaxf(tm0, __shfl_xor_sync(0xffffffffu, tm0, 1));
        tm0 = fmaxf(tm0, __shfl_xor_sync(0xffffffffu, tm0, 2));
        tm1 = fmaxf(tm1, __shfl_xor_sync(0xffffffffu, tm1, 1));
        tm1 = fmaxf(tm1, __shfl_xor_sync(0xffffffffu, tm1, 2));

        float mnew0 = fmaxf(mrow[0], tm0);
        float mnew1 = fmaxf(mrow[1], tm1);
        float corr0 = exp2f(mrow[0] - mnew0);
        float corr1 = exp2f(mrow[1] - mnew1);
        mrow[0] = mnew0;
        mrow[1] = mnew1;
#pragma unroll
        for (int nt = 0; nt < 8; nt++) {
            oacc[nt][0] *= corr0; oacc[nt][1] *= corr0;
            oacc[nt][2] *= corr1; oacc[nt][3] *= corr1;
        }

        uint32_t pf[4][4];
        float ps0 = 0.f, ps1 = 0.f;
#pragma unroll
        for (int nt = 0; nt < 8; nt++) {
            __half2 d0 = __floats2half2_rn(sacc[nt][0] - mnew0, sacc[nt][1] - mnew0);
            __half2 d1 = __floats2half2_rn(sacc[nt][2] - mnew1, sacc[nt][3] - mnew1);
            uint32_t p0 = h2exp2(*(uint32_t*)&d0);
            uint32_t p1 = h2exp2(*(uint32_t*)&d1);
            float2 f0 = __half22float2(*(__half2*)&p0);
            float2 f1 = __half22float2(*(__half2*)&p1);
            ps0 += f0.x + f0.y;
            ps1 += f1.x + f1.y;
            pf[nt >> 1][(nt & 1) * 2]     = p0;
            pf[nt >> 1][(nt & 1) * 2 + 1] = p1;
        }
        ps0 += __shfl_xor_sync(0xffffffffu, ps0, 1);
        ps0 += __shfl_xor_sync(0xffffffffu, ps0, 2);
        ps1 += __shfl_xor_sync(0xffffffffu, ps1, 1);
        ps1 += __shfl_xor_sync(0xffffffffu, ps1, 2);
        lrow[0] = lrow[0] * corr0 + ps0;
        lrow[1] = lrow[1] * corr1 + ps1;

        // O += P @ V : V tile stored [s][dv]; trans-ldmatrix -> B fragments
#pragma unroll
        for (int kc16 = 0; kc16 < 4; kc16++) {
            uint32_t vf[8][2];
#pragma unroll
            for (int nb = 0; nb < 4; nb++) {
                int srow = kc16 * 16 + (lm & 1) * 8 + lr;     // s row in tile
                int ch   = nb * 2 + (lm >> 1);                // dv chunk
                uint32_t ad = vb + (uint32_t)(srow << 7)
                            + ((uint32_t)(ch ^ (srow & 7)) << 4);
                LDSM_X4_T(vf[nb * 2][0], vf[nb * 2][1],
                          vf[nb * 2 + 1][0], vf[nb * 2 + 1][1], ad);
            }
#pragma unroll
            for (int nt = 0; nt < 8; nt++)
                MMA16816H(oacc[nt], pf[kc16][0], pf[kc16][1], pf[kc16][2], pf[kc16][3],
                          vf[nt][0], vf[nt][1]);
        }
    }

    float inv0 = 1.0f / lrow[0];
    float inv1 = 1.0f / lrow[1];
    size_t rt0 = (size_t)(b * SEQ + qt0 + w * 16 + g);
    __half* O0 = O + rt0 * EMB + h * 64;
    __half* O1 = O0 + (size_t)8 * EMB;
#pragma unroll
    for (int nt = 0; nt < 8; nt++) {
        int c = nt * 8 + 2 * tq;
        *(__half2*)&O0[c] = __floats2half2_rn(oacc[nt][0] * inv0, oacc[nt][1] * inv0);
        *(__half2*)&O1[c] = __floats2half2_rn(oacc[nt][2] * inv1, oacc[nt][3] * inv1);
    }
}

// ---------------------------------------------------------------------------
// launch
// ---------------------------------------------------------------------------
extern "C" void kernel_launch(void* const* d_in, const int* in_sizes, int n_in,
                              void* d_out, int out_size)
{
    const float* x   = (const float*)d_in[0];
    const float* Wq  = (const float*)d_in[1];
    const float* bq  = (const float*)d_in[2];
    const float* Wk  = (const float*)d_in[3];
    const float* bk  = (const float*)d_in[4];
    const float* Wv  = (const float*)d_in[5];
    const float* bv  = (const float*)d_in[6];
    const float* Wo  = (const float*)d_in[7];
    const float* bo  = (const float*)d_in[8];
    const float* J   = (const float*)d_in[9];
    const float* lam = (const float*)d_in[10];
    float* out = (float*)d_out;

    void* p = nullptr;
    cudaGetSymbolAddress(&p, g_hscratch);
    __half* hs    = (__half*)p;
    __half* x16   = hs + HX;
    __half* w16   = hs + HW;
    __half* qkv16 = hs + HQKV;
    __half* qc    = hs + HQC;
    __half* kc    = hs + HKC;
    __half* o16   = hs + HO;

    const int WSZ = EMB * EMB;
    __half* wo16 = w16 + 3 * WSZ;

    convert_kernel<<<(N_TOK * EMB / 4 + 255) / 256, 256>>>(x, x16, N_TOK * EMB / 4);
    dim3 tg(32, 32, 4), tb(256);
    transpose4_kernel<<<tg, tb>>>(Wq, Wk, Wv, Wo, w16);

    cudaFuncSetAttribute(gemm_fp16, cudaFuncAttributeMaxDynamicSharedMemorySize, GSMEM);
    gemm_fp16<<<dim3(24, 32), 256, GSMEM>>>(x16, w16, bq, bk, bv, qkv16, 3072, 1);

    dim3 prep_grid(N_TOK / 8, HEADS), prep_blk(64, 8);
    prep_kernel<<<prep_grid, prep_blk>>>(qkv16, J, lam, qc, kc);

    cudaFuncSetAttribute(flash16_kernel, cudaFuncAttributeMaxDynamicSharedMemorySize,
                         FL16_SMEM);
    dim3 fl_grid(SEQ / 128, BH);
    flash16_kernel<<<fl_grid, 256, FL16_SMEM>>>(qc, kc, qkv16, o16);

    gemm_fp16<<<dim3(8, 32), 256, GSMEM>>>(o16, wo16, bo, bo, bo, out, 1024, 0);
}